// round 10
// baseline (speedup 1.0000x reference)
#include <cuda_runtime.h>
#include <stdint.h>

// GCN layer, atomic-free aggregation via counting-sort by dst.
// src/dst are INT32 (JAX with x64 disabled).
//
// out = relu( (indeg>0 ? (sum_{e: dst=n} feat[src_e]*ci[src_e]) * cj[n]
//                      : feat[n]) @ W^T + b )

#define N_NODES   50000
#define N_EDGES   1600000
#define D         48
#define DV        12            // float4 chunks per row
#define SCAN_B    256
#define SCAN_G    ((N_NODES + SCAN_B - 1) / SCAN_B)   // 196
#define GF_NODES  16            // nodes per gather+finalize block
#define GF_T      (GF_NODES * DV)   // 192 threads

// Scratch (__device__ globals; no allocation allowed)
__device__ float4 g_featci[N_NODES * DV];    // 9.6 MB  feat * ci (premultiplied)
__device__ int    g_outdeg[N_NODES];
__device__ int    g_indeg[N_NODES];
__device__ int    g_off[N_NODES];            // exclusive prefix of indeg
__device__ int    g_cursor[N_NODES];         // bucket fill cursors
__device__ int    g_sorted_src[N_EDGES];     // src ids grouped by dst (6.4 MB)
__device__ int    g_blocksum[SCAN_G];
__device__ int    g_blockbase[SCAN_G];

__device__ __forceinline__ int clamp_node(int v) {
    return ((unsigned)v < (unsigned)N_NODES) ? v : 0;
}

// ---------------------------------------------------------------------------
__global__ void zero_kernel() {
    int i = blockIdx.x * blockDim.x + threadIdx.x;
    if (i < N_NODES) { g_outdeg[i] = 0; g_indeg[i] = 0; }
}

// ---------------------------------------------------------------------------
// 4 edges per thread via int4 loads.
__global__ void degree_kernel(const int4* __restrict__ src4,
                              const int4* __restrict__ dst4) {
    int t = blockIdx.x * blockDim.x + threadIdx.x;
    if (t >= N_EDGES / 4) return;
    int4 s = src4[t];
    int4 d = dst4[t];
    atomicAdd(&g_outdeg[clamp_node(s.x)], 1);
    atomicAdd(&g_outdeg[clamp_node(s.y)], 1);
    atomicAdd(&g_outdeg[clamp_node(s.z)], 1);
    atomicAdd(&g_outdeg[clamp_node(s.w)], 1);
    atomicAdd(&g_indeg[clamp_node(d.x)], 1);
    atomicAdd(&g_indeg[clamp_node(d.y)], 1);
    atomicAdd(&g_indeg[clamp_node(d.z)], 1);
    atomicAdd(&g_indeg[clamp_node(d.w)], 1);
}

// ---------------------------------------------------------------------------
// featci[n] = feat[n] * rsqrt(max(outdeg[n],1)), 12 threads per node
__global__ void premul_kernel(const float4* __restrict__ feat4) {
    unsigned idx = blockIdx.x * blockDim.x + threadIdx.x;
    if (idx >= (unsigned)N_NODES * DV) return;
    unsigned n = idx / DV;
    float ci = rsqrtf(fmaxf((float)g_outdeg[n], 1.0f));
    float4 v = feat4[idx];
    v.x *= ci; v.y *= ci; v.z *= ci; v.w *= ci;
    g_featci[idx] = v;
}

// ---------------------------------------------------------------------------
// Three-phase exclusive scan of g_indeg -> g_off, g_cursor
__global__ void scanA_kernel() {
    __shared__ int sh[SCAN_B];
    int i = blockIdx.x * SCAN_B + threadIdx.x;
    sh[threadIdx.x] = (i < N_NODES) ? g_indeg[i] : 0;
    __syncthreads();
    for (int off = SCAN_B / 2; off > 0; off >>= 1) {
        if (threadIdx.x < off) sh[threadIdx.x] += sh[threadIdx.x + off];
        __syncthreads();
    }
    if (threadIdx.x == 0) g_blocksum[blockIdx.x] = sh[0];
}

__global__ void scanB_kernel() {
    __shared__ int sh[SCAN_G];
    int t = threadIdx.x;
    if (t < SCAN_G) sh[t] = g_blocksum[t];
    __syncthreads();
    for (int off = 1; off < SCAN_G; off <<= 1) {
        int v = (t >= off && t < SCAN_G) ? sh[t - off] : 0;
        __syncthreads();
        if (t < SCAN_G) sh[t] += v;
        __syncthreads();
    }
    if (t < SCAN_G) g_blockbase[t] = (t == 0) ? 0 : sh[t - 1];
}

__global__ void scanC_kernel() {
    __shared__ int sh[SCAN_B];
    int i = blockIdx.x * SCAN_B + threadIdx.x;
    int t = threadIdx.x;
    int v = (i < N_NODES) ? g_indeg[i] : 0;
    sh[t] = v;
    __syncthreads();
    for (int off = 1; off < SCAN_B; off <<= 1) {
        int u = (t >= off) ? sh[t - off] : 0;
        __syncthreads();
        sh[t] += u;
        __syncthreads();
    }
    if (i < N_NODES) {
        int excl = g_blockbase[blockIdx.x] + sh[t] - v;
        g_off[i]    = excl;
        g_cursor[i] = excl;
    }
}

// ---------------------------------------------------------------------------
// Bucket edges by dst (4 edges/thread): sorted_src[pos] = src
__global__ void bucket_kernel(const int4* __restrict__ src4,
                              const int4* __restrict__ dst4) {
    int t = blockIdx.x * blockDim.x + threadIdx.x;
    if (t >= N_EDGES / 4) return;
    int4 s = src4[t];
    int4 d = dst4[t];
    int p;
    p = atomicAdd(&g_cursor[clamp_node(d.x)], 1);
    if ((unsigned)p < (unsigned)N_EDGES) g_sorted_src[p] = clamp_node(s.x);
    p = atomicAdd(&g_cursor[clamp_node(d.y)], 1);
    if ((unsigned)p < (unsigned)N_EDGES) g_sorted_src[p] = clamp_node(s.y);
    p = atomicAdd(&g_cursor[clamp_node(d.z)], 1);
    if ((unsigned)p < (unsigned)N_EDGES) g_sorted_src[p] = clamp_node(s.z);
    p = atomicAdd(&g_cursor[clamp_node(d.w)], 1);
    if ((unsigned)p < (unsigned)N_EDGES) g_sorted_src[p] = clamp_node(s.w);
}

// ---------------------------------------------------------------------------
// Fused gather + normalize + linear + relu.
// 16 nodes per 192-thread block; 12 threads per node, one float4 column each.
// Aggregated row staged in smem, then 48x48 GEMM from smem-cached W.
__global__ __launch_bounds__(GF_T) void gather_finalize_kernel(
        const float4* __restrict__ feat4,
        const float*  __restrict__ W,
        const float*  __restrict__ b,
        float*        __restrict__ out) {
    __shared__ float Ws[D * D];        // 9.2 KB
    __shared__ float bs[D];
    __shared__ float hs[GF_NODES][D];  // 3 KB

    int tid = threadIdx.x;
    for (int i = tid; i < D * D; i += GF_T) Ws[i] = W[i];
    if (tid < D) bs[tid] = b[tid];

    int ln = tid / DV;                 // local node 0..15
    int c  = tid - ln * DV;            // float4 column 0..11
    unsigned n = blockIdx.x * GF_NODES + ln;
    bool valid = (n < (unsigned)N_NODES);

    float4 h = make_float4(0.f, 0.f, 0.f, 0.f);
    if (valid) {
        int beg = g_off[n];
        int cnt = g_indeg[n];

        float4 acc = make_float4(0.f, 0.f, 0.f, 0.f);
        int k = 0;
        for (; k + 4 <= cnt; k += 4) {
            int s0 = g_sorted_src[beg + k + 0];
            int s1 = g_sorted_src[beg + k + 1];
            int s2 = g_sorted_src[beg + k + 2];
            int s3 = g_sorted_src[beg + k + 3];
            float4 v0 = g_featci[(unsigned)s0 * DV + c];
            float4 v1 = g_featci[(unsigned)s1 * DV + c];
            float4 v2 = g_featci[(unsigned)s2 * DV + c];
            float4 v3 = g_featci[(unsigned)s3 * DV + c];
            acc.x += v0.x + v1.x + v2.x + v3.x;
            acc.y += v0.y + v1.y + v2.y + v3.y;
            acc.z += v0.z + v1.z + v2.z + v3.z;
            acc.w += v0.w + v1.w + v2.w + v3.w;
        }
        for (; k < cnt; k++) {
            int s0 = g_sorted_src[beg + k];
            float4 v0 = g_featci[(unsigned)s0 * DV + c];
            acc.x += v0.x; acc.y += v0.y; acc.z += v0.z; acc.w += v0.w;
        }

        if (cnt > 0) {
            float cj = rsqrtf((float)cnt);
            h.x = acc.x * cj; h.y = acc.y * cj;
            h.z = acc.z * cj; h.w = acc.w * cj;
        } else {
            h = feat4[n * DV + c];     // zero-in-degree: keep original features
        }
        hs[ln][c * 4 + 0] = h.x;
        hs[ln][c * 4 + 1] = h.y;
        hs[ln][c * 4 + 2] = h.z;
        hs[ln][c * 4 + 3] = h.w;
    }
    __syncthreads();

    if (valid) {
        int o0 = c * 4;                // this thread computes outputs o0..o0+3
        float a0 = bs[o0 + 0], a1 = bs[o0 + 1], a2 = bs[o0 + 2], a3 = bs[o0 + 3];
#pragma unroll 8
        for (int i = 0; i < D; i++) {
            float hi = hs[ln][i];
            a0 += hi * Ws[(o0 + 0) * D + i];
            a1 += hi * Ws[(o0 + 1) * D + i];
            a2 += hi * Ws[(o0 + 2) * D + i];
            a3 += hi * Ws[(o0 + 3) * D + i];
        }
        float4 r;
        r.x = fmaxf(a0, 0.f); r.y = fmaxf(a1, 0.f);
        r.z = fmaxf(a2, 0.f); r.w = fmaxf(a3, 0.f);
        ((float4*)(out + (size_t)n * D))[c] = r;
    }
}

// ---------------------------------------------------------------------------
extern "C" void kernel_launch(void* const* d_in, const int* in_sizes, int n_in,
                              void* d_out, int out_size) {
    const float* feat = (const float*)d_in[0];
    const int*   src  = (const int*)d_in[1];    // int32
    const int*   dst  = (const int*)d_in[2];
    const float* W    = (const float*)d_in[3];
    const float* b    = (const float*)d_in[4];
    float*       out  = (float*)d_out;
    (void)in_sizes; (void)n_in; (void)out_size;

    const int TB = 256;

    zero_kernel<<<(N_NODES + TB - 1) / TB, TB>>>();
    degree_kernel<<<(N_EDGES / 4 + TB - 1) / TB, TB>>>(
        (const int4*)src, (const int4*)dst);
    {
        unsigned total = (unsigned)N_NODES * DV;   // 600000
        premul_kernel<<<(total + TB - 1) / TB, TB>>>((const float4*)feat);
    }
    scanA_kernel<<<SCAN_G, SCAN_B>>>();
    scanB_kernel<<<1, SCAN_B>>>();
    scanC_kernel<<<SCAN_G, SCAN_B>>>();
    bucket_kernel<<<(N_EDGES / 4 + TB - 1) / TB, TB>>>(
        (const int4*)src, (const int4*)dst);
    gather_finalize_kernel<<<(N_NODES + GF_NODES - 1) / GF_NODES, GF_T>>>(
        (const float4*)feat, W, b, out);
}

// round 11
// speedup vs baseline: 1.6174x; 1.6174x over previous
#include <cuda_runtime.h>
#include <cuda_fp16.h>
#include <stdint.h>

// GCN layer, atomic-free aggregation via counting-sort by dst.
// src/dst are INT32 (JAX with x64 disabled).
// R11: exact R7 structure (103.2us proven), with the premultiplied feature
// table stored in fp16 to halve gather L2 traffic. Accumulation is fp32;
// zero-in-degree identity path stays exact fp32.

#define N_NODES   50000
#define N_EDGES   1600000
#define D         48
#define DV        12            // float4 chunks per row
#define HDV       6             // uint4 (8-half) chunks per row
#define SCAN_B    256
#define SCAN_G    ((N_NODES + SCAN_B - 1) / SCAN_B)   // 196

// Scratch (__device__ globals; no allocation allowed)
__device__ float4 g_agg[N_NODES * DV];       // 9.6 MB aggregated messages (fp32)
__device__ uint4  g_featci_h[N_NODES * HDV]; // 4.8 MB feat*ci in fp16 (8 halves/uint4)
__device__ int    g_outdeg[N_NODES];
__device__ int    g_indeg[N_NODES];
__device__ int    g_off[N_NODES];            // exclusive prefix of indeg
__device__ int    g_cursor[N_NODES];         // bucket fill cursors
__device__ int    g_sorted_src[N_EDGES];     // src ids grouped by dst (6.4 MB)
__device__ int    g_blocksum[SCAN_G];
__device__ int    g_blockbase[SCAN_G];

__device__ __forceinline__ int clamp_node(int v) {
    return ((unsigned)v < (unsigned)N_NODES) ? v : 0;
}

// ---------------------------------------------------------------------------
__global__ void zero_kernel() {
    int i = blockIdx.x * blockDim.x + threadIdx.x;
    if (i < N_NODES) { g_outdeg[i] = 0; g_indeg[i] = 0; }
}

// ---------------------------------------------------------------------------
__global__ void degree_kernel(const int* __restrict__ src,
                              const int* __restrict__ dst) {
    int e = blockIdx.x * blockDim.x + threadIdx.x;
    if (e >= N_EDGES) return;
    atomicAdd(&g_outdeg[clamp_node(src[e])], 1);
    atomicAdd(&g_indeg[clamp_node(dst[e])], 1);
}

// ---------------------------------------------------------------------------
// featci_h[n] = fp16(feat[n] * rsqrt(max(outdeg[n],1))), 6 threads per node.
// Each thread converts 8 floats (2 float4) -> 1 uint4 of halves.
__global__ void premul_kernel(const float4* __restrict__ feat4) {
    unsigned idx = blockIdx.x * blockDim.x + threadIdx.x;
    if (idx >= (unsigned)N_NODES * HDV) return;
    unsigned n = idx / HDV;
    unsigned c = idx - n * HDV;
    float ci = rsqrtf(fmaxf((float)g_outdeg[n], 1.0f));
    float4 v0 = feat4[n * DV + c * 2 + 0];
    float4 v1 = feat4[n * DV + c * 2 + 1];
    uint4 o;
    __half2* ph = (__half2*)&o;
    ph[0] = __floats2half2_rn(v0.x * ci, v0.y * ci);
    ph[1] = __floats2half2_rn(v0.z * ci, v0.w * ci);
    ph[2] = __floats2half2_rn(v1.x * ci, v1.y * ci);
    ph[3] = __floats2half2_rn(v1.z * ci, v1.w * ci);
    g_featci_h[idx] = o;
}

// ---------------------------------------------------------------------------
// Three-phase exclusive scan of g_indeg -> g_off, g_cursor
__global__ void scanA_kernel() {
    __shared__ int sh[SCAN_B];
    int i = blockIdx.x * SCAN_B + threadIdx.x;
    sh[threadIdx.x] = (i < N_NODES) ? g_indeg[i] : 0;
    __syncthreads();
    for (int off = SCAN_B / 2; off > 0; off >>= 1) {
        if (threadIdx.x < off) sh[threadIdx.x] += sh[threadIdx.x + off];
        __syncthreads();
    }
    if (threadIdx.x == 0) g_blocksum[blockIdx.x] = sh[0];
}

__global__ void scanB_kernel() {
    __shared__ int sh[SCAN_G];
    int t = threadIdx.x;
    if (t < SCAN_G) sh[t] = g_blocksum[t];
    __syncthreads();
    for (int off = 1; off < SCAN_G; off <<= 1) {
        int v = (t >= off && t < SCAN_G) ? sh[t - off] : 0;
        __syncthreads();
        if (t < SCAN_G) sh[t] += v;
        __syncthreads();
    }
    if (t < SCAN_G) g_blockbase[t] = (t == 0) ? 0 : sh[t - 1];
}

__global__ void scanC_kernel() {
    __shared__ int sh[SCAN_B];
    int i = blockIdx.x * SCAN_B + threadIdx.x;
    int t = threadIdx.x;
    int v = (i < N_NODES) ? g_indeg[i] : 0;
    sh[t] = v;
    __syncthreads();
    for (int off = 1; off < SCAN_B; off <<= 1) {
        int u = (t >= off) ? sh[t - off] : 0;
        __syncthreads();
        sh[t] += u;
        __syncthreads();
    }
    if (i < N_NODES) {
        int excl = g_blockbase[blockIdx.x] + sh[t] - v;
        g_off[i]    = excl;
        g_cursor[i] = excl;
    }
}

// ---------------------------------------------------------------------------
// Bucket edges by dst: sorted_src[pos] = src
__global__ void bucket_kernel(const int* __restrict__ src,
                              const int* __restrict__ dst) {
    int e = blockIdx.x * blockDim.x + threadIdx.x;
    if (e >= N_EDGES) return;
    int d = clamp_node(dst[e]);
    int pos = atomicAdd(&g_cursor[d], 1);
    if ((unsigned)pos < (unsigned)N_EDGES)
        g_sorted_src[pos] = clamp_node(src[e]);
}

// ---------------------------------------------------------------------------
// Atomic-free gather: 6 threads per node, thread owns 8 halves (one uint4).
// fp32 accumulation, writes fp32 g_agg.
__global__ void gather_kernel() {
    unsigned idx = blockIdx.x * blockDim.x + threadIdx.x;
    if (idx >= (unsigned)N_NODES * HDV) return;
    unsigned n = idx / HDV;
    unsigned c = idx - n * HDV;

    int beg = g_off[n];
    int cnt = g_indeg[n];

    float a0 = 0.f, a1 = 0.f, a2 = 0.f, a3 = 0.f;
    float a4 = 0.f, a5 = 0.f, a6 = 0.f, a7 = 0.f;

    int k = 0;
    for (; k + 2 <= cnt; k += 2) {
        int s0 = g_sorted_src[beg + k + 0];
        int s1 = g_sorted_src[beg + k + 1];
        uint4 v0 = g_featci_h[(unsigned)s0 * HDV + c];
        uint4 v1 = g_featci_h[(unsigned)s1 * HDV + c];
        const __half2* p0 = (const __half2*)&v0;
        const __half2* p1 = (const __half2*)&v1;
        float2 f;
        f = __half22float2(p0[0]); a0 += f.x; a1 += f.y;
        f = __half22float2(p0[1]); a2 += f.x; a3 += f.y;
        f = __half22float2(p0[2]); a4 += f.x; a5 += f.y;
        f = __half22float2(p0[3]); a6 += f.x; a7 += f.y;
        f = __half22float2(p1[0]); a0 += f.x; a1 += f.y;
        f = __half22float2(p1[1]); a2 += f.x; a3 += f.y;
        f = __half22float2(p1[2]); a4 += f.x; a5 += f.y;
        f = __half22float2(p1[3]); a6 += f.x; a7 += f.y;
    }
    if (k < cnt) {
        int s0 = g_sorted_src[beg + k];
        uint4 v0 = g_featci_h[(unsigned)s0 * HDV + c];
        const __half2* p0 = (const __half2*)&v0;
        float2 f;
        f = __half22float2(p0[0]); a0 += f.x; a1 += f.y;
        f = __half22float2(p0[1]); a2 += f.x; a3 += f.y;
        f = __half22float2(p0[2]); a4 += f.x; a5 += f.y;
        f = __half22float2(p0[3]); a6 += f.x; a7 += f.y;
    }

    g_agg[n * DV + c * 2 + 0] = make_float4(a0, a1, a2, a3);
    g_agg[n * DV + c * 2 + 1] = make_float4(a4, a5, a6, a7);
}

// ---------------------------------------------------------------------------
// h = indeg>0 ? agg*cj : feat ; out = relu(h @ W^T + b)
// Thread-per-node: W reads are warp-uniform -> smem broadcast, conflict-free.
__global__ void finalize_kernel(const float* __restrict__ feat,
                                const float* __restrict__ W,
                                const float* __restrict__ b,
                                float* __restrict__ out) {
    __shared__ float Ws[D * D];
    __shared__ float bs[D];
    for (int i = threadIdx.x; i < D * D; i += blockDim.x) Ws[i] = W[i];
    if (threadIdx.x < D) bs[threadIdx.x] = b[threadIdx.x];
    __syncthreads();

    int n = blockIdx.x * blockDim.x + threadIdx.x;
    if (n >= N_NODES) return;

    int indeg = g_indeg[n];
    float cj = rsqrtf(fmaxf((float)indeg, 1.0f));
    const float* aggp = (const float*)g_agg;
    const float* hp   = (indeg > 0) ? (aggp + (size_t)n * D) : (feat + (size_t)n * D);
    float scale       = (indeg > 0) ? cj : 1.0f;

    float acc[D];
#pragma unroll
    for (int o = 0; o < D; o++) acc[o] = bs[o];

#pragma unroll 4
    for (int i = 0; i < D; i++) {
        float hi = hp[i] * scale;
#pragma unroll
        for (int o = 0; o < D; o++) acc[o] += hi * Ws[o * D + i];
    }

    float4* out4 = (float4*)(out + (size_t)n * D);
#pragma unroll
    for (int k = 0; k < DV; k++) {
        float4 v;
        v.x = fmaxf(acc[4 * k + 0], 0.f);
        v.y = fmaxf(acc[4 * k + 1], 0.f);
        v.z = fmaxf(acc[4 * k + 2], 0.f);
        v.w = fmaxf(acc[4 * k + 3], 0.f);
        out4[k] = v;
    }
}

// ---------------------------------------------------------------------------
extern "C" void kernel_launch(void* const* d_in, const int* in_sizes, int n_in,
                              void* d_out, int out_size) {
    const float* feat = (const float*)d_in[0];
    const int*   src  = (const int*)d_in[1];    // int32
    const int*   dst  = (const int*)d_in[2];
    const float* W    = (const float*)d_in[3];
    const float* b    = (const float*)d_in[4];
    float*       out  = (float*)d_out;
    (void)in_sizes; (void)n_in; (void)out_size;

    const int TB = 256;

    zero_kernel<<<(N_NODES + TB - 1) / TB, TB>>>();
    degree_kernel<<<(N_EDGES + TB - 1) / TB, TB>>>(src, dst);
    {
        unsigned total = (unsigned)N_NODES * HDV;   // 300000
        premul_kernel<<<(total + TB - 1) / TB, TB>>>((const float4*)feat);
    }
    scanA_kernel<<<SCAN_G, SCAN_B>>>();
    scanB_kernel<<<1, SCAN_B>>>();
    scanC_kernel<<<SCAN_G, SCAN_B>>>();
    bucket_kernel<<<(N_EDGES + TB - 1) / TB, TB>>>(src, dst);
    {
        unsigned total = (unsigned)N_NODES * HDV;   // 300000
        gather_kernel<<<(total + 191) / 192, 192>>>();
    }
    finalize_kernel<<<(N_NODES + TB - 1) / TB, TB>>>(feat, W, b, out);
}